// round 3
// baseline (speedup 1.0000x reference)
#include <cuda_runtime.h>

#define BATCH 32
#define CH 4
#define SEQ 256
#define FD 256
#define SS (SEQ * SEQ)
#define TOTAL_RAND (BATCH * SS * 2u)

// Scratch (static device globals -- no runtime allocation)
__device__ float g_adj[BATCH * SS];                 // binary adjacency, diag forced 1
__device__ float g_rowinv[BATCH * SEQ];             // 1 / rowsum (fp32 RN)
__device__ float g_X[BATCH * CH * SEQ * FD];        // adjn @ features

// ---------------------------------------------------------------------------
// Threefry-2x32 (JAX PRNG), key = (0, 42) from jax.random.key(42)
// ---------------------------------------------------------------------------
__device__ __forceinline__ void threefry(unsigned x0, unsigned x1,
                                         unsigned& o0, unsigned& o1) {
    const unsigned k0 = 0u, k1 = 42u;
    const unsigned ks2 = k0 ^ k1 ^ 0x1BD11BDAu;
#define TFR(v, r) v = ((v << r) | (v >> (32 - r)))
#define QROUND(a, b, c, d)                                   \
    x0 += x1; TFR(x1, a); x1 ^= x0;                          \
    x0 += x1; TFR(x1, b); x1 ^= x0;                          \
    x0 += x1; TFR(x1, c); x1 ^= x0;                          \
    x0 += x1; TFR(x1, d); x1 ^= x0
    x0 += k0;  x1 += k1;
    QROUND(13, 15, 26, 6);
    x0 += k1;  x1 += ks2 + 1u;
    QROUND(17, 29, 16, 24);
    x0 += ks2; x1 += k0 + 2u;
    QROUND(13, 15, 26, 6);
    x0 += k0;  x1 += k1 + 3u;
    QROUND(17, 29, 16, 24);
    x0 += k1;  x1 += ks2 + 4u;
    QROUND(13, 15, 26, 6);
    x0 += ks2; x1 += k0 + 5u;
    o0 = x0; o1 = x1;
#undef QROUND
#undef TFR
}

// JAX threefry counter mode: 1 = partitionable (default since jax 0.4.36),
// 0 = original split-halves mode. rel_err=1.3e-2 (not O(1)) confirms mode 1.
#ifndef JAX_THREEFRY_PARTITIONABLE
#define JAX_THREEFRY_PARTITIONABLE 1
#endif

__device__ __forceinline__ float gumbel_at(unsigned idx) {
    unsigned bits;
#if JAX_THREEFRY_PARTITIONABLE
    unsigned o0, o1;
    threefry(0u, idx, o0, o1);           // counter = uint64 idx -> (hi=0, lo=idx)
    bits = o0 ^ o1;
#else
    const unsigned H = TOTAL_RAND >> 1;
    unsigned o0, o1;
    if (idx < H) { threefry(idx, idx + H, o0, o1); bits = o0; }
    else         { threefry(idx - H, idx, o0, o1); bits = o1; }
#endif
    // jax.random.uniform: f in [0,1) from top 23 bits; u = max(1e-10, f*(1-1e-10)+1e-10)
    float f = __uint_as_float((bits >> 9) | 0x3F800000u) - 1.0f;
    float u = fmaxf(1e-10f, f + 1e-10f);   // (maxval-minval) rounds to 1.0f in fp32
    return -logf(-logf(u));
}

// exact-erf GELU, matching jax.nn.gelu(approximate=False) op order
__device__ __forceinline__ float gelu_exact(float x) {
    float t = __fdiv_rn(x, 1.41421356f);   // np.sqrt(2) as f32, RN division
    return x * (erff(t) + 1.0f) * 0.5f;
}

// ---------------------------------------------------------------------------
// Kernel 1: corr GEMM (full fp32) fused with MLP + gumbel argmax decision
// grid (8,8,32), block (32,8); each thread computes 4 (s,t) entries
// ---------------------------------------------------------------------------
__global__ __launch_bounds__(256) void adj_kernel(
    const float* __restrict__ fm,
    const float* __restrict__ W1, const float* __restrict__ b1,
    const float* __restrict__ W2, const float* __restrict__ b2,
    const float* __restrict__ W3, const float* __restrict__ b3)
{
    __shared__ float As[32][33];
    __shared__ float At[32][33];
    __shared__ float sW1[16], sb1[16], sW2[128], sb2[8], sW3[16], sb3[2];

    const int tx = threadIdx.x, ty = threadIdx.y;
    const int tid = ty * 32 + tx;
    const int b  = blockIdx.z;
    const int s0 = blockIdx.y * 32, t0 = blockIdx.x * 32;

    if (tid < 16) { sW1[tid] = W1[tid]; sb1[tid] = b1[tid]; sW3[tid] = W3[tid]; }
    if (tid >= 32 && tid < 160)  sW2[tid - 32]  = W2[tid - 32];
    if (tid >= 160 && tid < 168) sb2[tid - 160] = b2[tid - 160];
    if (tid >= 168 && tid < 170) sb3[tid - 168] = b3[tid - 168];

    const float* A = fm + (size_t)b * SEQ * FD;
    float acc[4] = {0.f, 0.f, 0.f, 0.f};

    for (int k0 = 0; k0 < FD; k0 += 32) {
        #pragma unroll
        for (int i = 0; i < 4; i++) {
            As[ty + 8 * i][tx] = A[(s0 + ty + 8 * i) * FD + k0 + tx];
            At[ty + 8 * i][tx] = A[(t0 + ty + 8 * i) * FD + k0 + tx];
        }
        __syncthreads();
        #pragma unroll
        for (int k = 0; k < 32; k++) {
            float bv = At[tx][k];
            #pragma unroll
            for (int i = 0; i < 4; i++)
                acc[i] = fmaf(As[ty + 8 * i][k], bv, acc[i]);
        }
        __syncthreads();
    }

    #pragma unroll
    for (int i = 0; i < 4; i++) {
        float c = acc[i];
        float h1[16];
        #pragma unroll
        for (int q = 0; q < 16; q++) h1[q] = gelu_exact(fmaf(c, sW1[q], sb1[q]));
        float h2[8];
        #pragma unroll
        for (int j = 0; j < 8; j++) {
            float p = sb2[j];
            #pragma unroll
            for (int q = 0; q < 16; q++) p = fmaf(h1[q], sW2[q * 8 + j], p);
            h2[j] = gelu_exact(p);
        }
        float l0 = sb3[0], l1 = sb3[1];
        #pragma unroll
        for (int j = 0; j < 8; j++) {
            l0 = fmaf(h2[j], sW3[2 * j + 0], l0);
            l1 = fmaf(h2[j], sW3[2 * j + 1], l1);
        }
        // log_softmax is a per-element constant shift -> argmax unchanged
        const int sr = s0 + ty + 8 * i;
        const int tc = t0 + tx;
        const unsigned p = (unsigned)b * SS + (unsigned)sr * SEQ + (unsigned)tc;
        float g0 = gumbel_at(2u * p);
        float g1 = gumbel_at(2u * p + 1u);
        float val = (l0 + g0 >= l1 + g1) ? 1.0f : 0.0f;  // argmax ties -> class 0
        if (sr == tc) val = 1.0f;                        // a + (1-a)*I
        g_adj[p] = val;
    }
}

// ---------------------------------------------------------------------------
// Kernel 2: row sums (exact: integer-valued) -> reciprocal
// ---------------------------------------------------------------------------
__global__ __launch_bounds__(256) void rowsum_kernel() {
    const int row = blockIdx.x;  // b*SEQ + s
    float v = g_adj[(size_t)row * SEQ + threadIdx.x];
    #pragma unroll
    for (int o = 16; o > 0; o >>= 1) v += __shfl_xor_sync(0xFFFFFFFFu, v, o);
    __shared__ float sm[8];
    if ((threadIdx.x & 31) == 0) sm[threadIdx.x >> 5] = v;
    __syncthreads();
    if (threadIdx.x == 0) {
        float s = 0.f;
        #pragma unroll
        for (int w = 0; w < 8; w++) s += sm[w];
        g_rowinv[row] = __frcp_rn(s);   // matches 1.0/sum with RN
    }
}

// ---------------------------------------------------------------------------
// Kernels 3/4: 128x128x8 tiled fp32 GEMM, 8x8 per thread
// ---------------------------------------------------------------------------
#define BM 128
#define BN 128
#define BKK 8

__global__ __launch_bounds__(256) void prop_kernel(const float* __restrict__ features) {
    const int z = blockIdx.z;            // b*4 + c
    const int b = z >> 2;
    const float* Aadj = g_adj + (size_t)b * SS;
    const float* Bf   = features + (size_t)z * SEQ * FD;
    float* Cx         = g_X + (size_t)z * SEQ * FD;
    const int m0 = blockIdx.y * BM, n0 = blockIdx.x * BN;

    __shared__ float As[BKK][BM + 4];
    __shared__ float Bs[BKK][BN + 4];
    __shared__ float rsc[BM];

    const int tid = threadIdx.x;
    if (tid < BM) rsc[tid] = g_rowinv[b * SEQ + m0 + tid];
    __syncthreads();

    const int alm = tid >> 1, alk = (tid & 1) * 4;
    const int bk = tid >> 5,  bn  = (tid & 31) * 4;
    const int ty = tid >> 4,  tx  = tid & 15;

    float acc[8][8];
    #pragma unroll
    for (int i = 0; i < 8; i++)
        #pragma unroll
        for (int j = 0; j < 8; j++) acc[i][j] = 0.f;

    for (int k0 = 0; k0 < SEQ; k0 += BKK) {
        float4 av = *reinterpret_cast<const float4*>(&Aadj[(size_t)(m0 + alm) * SEQ + k0 + alk]);
        float r = rsc[alm];                  // adjn entry = bit * (1/k), exact product
        As[alk + 0][alm] = av.x * r;
        As[alk + 1][alm] = av.y * r;
        As[alk + 2][alm] = av.z * r;
        As[alk + 3][alm] = av.w * r;
        float4 bv = *reinterpret_cast<const float4*>(&Bf[(size_t)(k0 + bk) * FD + n0 + bn]);
        Bs[bk][bn + 0] = bv.x;
        Bs[bk][bn + 1] = bv.y;
        Bs[bk][bn + 2] = bv.z;
        Bs[bk][bn + 3] = bv.w;
        __syncthreads();
        #pragma unroll
        for (int kk = 0; kk < BKK; kk++) {
            float a[8], bb[8];
            #pragma unroll
            for (int i = 0; i < 8; i++) a[i] = As[kk][ty * 8 + i];
            #pragma unroll
            for (int j = 0; j < 8; j++) bb[j] = Bs[kk][tx * 8 + j];
            #pragma unroll
            for (int i = 0; i < 8; i++)
                #pragma unroll
                for (int j = 0; j < 8; j++)
                    acc[i][j] = fmaf(a[i], bb[j], acc[i][j]);
        }
        __syncthreads();
    }
    #pragma unroll
    for (int i = 0; i < 8; i++) {
        float* cp = &Cx[(size_t)(m0 + ty * 8 + i) * FD + n0 + tx * 8];
        *reinterpret_cast<float4*>(cp)     = make_float4(acc[i][0], acc[i][1], acc[i][2], acc[i][3]);
        *reinterpret_cast<float4*>(cp + 4) = make_float4(acc[i][4], acc[i][5], acc[i][6], acc[i][7]);
    }
}

__global__ __launch_bounds__(256) void out_kernel(const float* __restrict__ Wl,
                                                  const float* __restrict__ bl,
                                                  float* __restrict__ out) {
    const int m0 = blockIdx.y * BM, n0 = blockIdx.x * BN;  // M = 32768, N = 256

    __shared__ float As[BKK][BM + 4];
    __shared__ float Bs[BKK][BN + 4];

    const int tid = threadIdx.x;
    const int alm = tid >> 1, alk = (tid & 1) * 4;
    const int bk = tid >> 5,  bn  = (tid & 31) * 4;
    const int ty = tid >> 4,  tx  = tid & 15;

    float acc[8][8];
    #pragma unroll
    for (int i = 0; i < 8; i++)
        #pragma unroll
        for (int j = 0; j < 8; j++) acc[i][j] = 0.f;

    for (int k0 = 0; k0 < FD; k0 += BKK) {
        float4 av = *reinterpret_cast<const float4*>(&g_X[(size_t)(m0 + alm) * FD + k0 + alk]);
        As[alk + 0][alm] = av.x;
        As[alk + 1][alm] = av.y;
        As[alk + 2][alm] = av.z;
        As[alk + 3][alm] = av.w;
        float4 bv = *reinterpret_cast<const float4*>(&Wl[(size_t)(k0 + bk) * FD + n0 + bn]);
        Bs[bk][bn + 0] = bv.x;
        Bs[bk][bn + 1] = bv.y;
        Bs[bk][bn + 2] = bv.z;
        Bs[bk][bn + 3] = bv.w;
        __syncthreads();
        #pragma unroll
        for (int kk = 0; kk < BKK; kk++) {
            float a[8], bb[8];
            #pragma unroll
            for (int i = 0; i < 8; i++) a[i] = As[kk][ty * 8 + i];
            #pragma unroll
            for (int j = 0; j < 8; j++) bb[j] = Bs[kk][tx * 8 + j];
            #pragma unroll
            for (int i = 0; i < 8; i++)
                #pragma unroll
                for (int j = 0; j < 8; j++)
                    acc[i][j] = fmaf(a[i], bb[j], acc[i][j]);
        }
        __syncthreads();
    }

    float blv[8];
    #pragma unroll
    for (int j = 0; j < 8; j++) blv[j] = bl[n0 + tx * 8 + j];

    #pragma unroll
    for (int i = 0; i < 8; i++) {
        float* cp = &out[(size_t)(m0 + ty * 8 + i) * FD + n0 + tx * 8];
        *reinterpret_cast<float4*>(cp)     = make_float4(acc[i][0] + blv[0], acc[i][1] + blv[1],
                                                         acc[i][2] + blv[2], acc[i][3] + blv[3]);
        *reinterpret_cast<float4*>(cp + 4) = make_float4(acc[i][4] + blv[4], acc[i][5] + blv[5],
                                                         acc[i][6] + blv[6], acc[i][7] + blv[7]);
    }
}

// ---------------------------------------------------------------------------
extern "C" void kernel_launch(void* const* d_in, const int* in_sizes, int n_in,
                              void* d_out, int out_size) {
    const float* features = (const float*)d_in[0];
    const float* fm       = (const float*)d_in[1];
    const float* W1       = (const float*)d_in[2];
    const float* b1       = (const float*)d_in[3];
    const float* W2       = (const float*)d_in[4];
    const float* b2       = (const float*)d_in[5];
    const float* W3       = (const float*)d_in[6];
    const float* b3       = (const float*)d_in[7];
    const float* Wl       = (const float*)d_in[8];
    const float* bl       = (const float*)d_in[9];
    float* out            = (float*)d_out;
    (void)in_sizes; (void)n_in; (void)out_size;

    adj_kernel<<<dim3(8, 8, BATCH), dim3(32, 8)>>>(fm, W1, b1, W2, b2, W3, b3);
    rowsum_kernel<<<BATCH * SEQ, 256>>>();
    prop_kernel<<<dim3(2, 2, BATCH * CH), 256>>>(features);
    out_kernel<<<dim3(2, BATCH * CH * SEQ / BM), 256>>>(Wl, bl, out);
}